// round 16
// baseline (speedup 1.0000x reference)
#include <cuda_runtime.h>
#include <math.h>

#define NG 256
#define IMG_H 512
#define IMG_W 512
#define RBLK 64    // 1024 blocks of 64 threads; each block = 64x4-pixel tile

// 1/(2*ln(2)) : folds exp(-0.5*mahal) -> single ex2; cancels inside tau.
#define S_CONST 0.7213475204444817f

typedef unsigned long long u64;

__device__ __forceinline__ u64 pk(float lo, float hi) {
    u64 r; asm("mov.b64 %0, {%1, %2};" : "=l"(r) : "f"(lo), "f"(hi)); return r;
}
__device__ __forceinline__ void upk(u64 v, float& lo, float& hi) {
    asm("mov.b64 {%0, %1}, %2;" : "=f"(lo), "=f"(hi) : "l"(v));
}
__device__ __forceinline__ u64 dup2(float x) { return pk(x, x); }
__device__ __forceinline__ u64 f2mul(u64 a, u64 b) {
    u64 r; asm("mul.rn.f32x2 %0, %1, %2;" : "=l"(r) : "l"(a), "l"(b)); return r;
}
__device__ __forceinline__ u64 f2fma(u64 a, u64 b, u64 c) {
    u64 r; asm("fma.rn.f32x2 %0, %1, %2, %3;" : "=l"(r) : "l"(a), "l"(b), "l"(c)); return r;
}
__device__ __forceinline__ float rcpa(float x) {
    float r; asm("rcp.approx.f32 %0, %1;" : "=f"(r) : "f"(x)); return r;
}
__device__ __forceinline__ float ex2a(float x) {
    float r; asm("ex2.approx.f32 %0, %1;" : "=f"(r) : "f"(x)); return r;
}

// 4 pixels per thread: one column, rows v0..v0+3 as TWO independent packed
// chains (A: rows 0,1 / B: rows 2,3). One set of gaussian loads feeds both.
struct Ray4 {
    u64 d0, dd0;          // shared column terms
    u64 d1a, dd1a, ntpa;  // chain A
    u64 d1b, dd1b, ntpb;  // chain B
};

__device__ __forceinline__ void comp_step4(const ulonglong2* __restrict__ L,
                                           const Ray4& r,
                                           u64& Ta, u64& i0a, u64& i1a, u64& i2a,
                                           u64& Tb, u64& i0b, u64& i1b, u64& i2b) {
    const u64 HUGE2 = 0x7E9676997E967699ull;   // dup2(1e38f)
    const u64 NEG1  = 0xBF800000BF800000ull;   // dup2(-1.0f)

    ulonglong2 L0 = L[0];
    ulonglong2 L1 = L[1];
    ulonglong2 L2 = L[2];
    ulonglong2 L3 = L[3];
    ulonglong2 L4 = L[4];

    // shared column partials: q0*dx + q2 ; s0*dx^2 + s2
    u64 nbase = f2fma(r.d0,  L0.x, L1.x);
    u64 dbase = f2fma(r.dd0, L1.y, L2.y);

    u64 numA = f2fma(r.d1a, L0.y, nbase);
    u64 numB = f2fma(r.d1b, L0.y, nbase);
    u64 denA = f2fma(r.dd1a, L2.x, dbase);
    u64 denB = f2fma(r.dd1b, L2.x, dbase);

    // margin m > 0 <=> tau > 0.1; gate = m*1e38
    u64 gateA = f2mul(f2fma(denA, r.ntpa, numA), HUGE2);
    u64 gateB = f2mul(f2fma(denB, r.ntpb, numB), HUGE2);

    float da0, da1, db0, db1;
    upk(denA, da0, da1);
    upk(denB, db0, db1);
    u64 rpA = pk(rcpa(da0), rcpa(da1));
    u64 rpB = pk(rcpa(db0), rcpa(db1));

    // e = num^2/den + kcol  (always <= log2 a0 < 0 by Cauchy-Schwarz)
    u64 eA = f2fma(numA, f2mul(numA, rpA), L3.x);
    u64 eB = f2fma(numB, f2mul(numB, rpB), L3.x);

    float ea0, ea1, eb0, eb1, ga0, ga1, gb0, gb1;
    upk(eA, ea0, ea1); upk(gateA, ga0, ga1);
    upk(eB, eb0, eb1); upk(gateB, gb0, gb1);
    u64 exA = pk(ex2a(fminf(ea0, ga0)), ex2a(fminf(ea1, ga1)));
    u64 exB = pk(ex2a(fminf(eb0, gb0)), ex2a(fminf(eb1, gb1)));

    u64 wA = f2mul(Ta, exA);
    u64 wB = f2mul(Tb, exB);
    i0a = f2fma(wA, L3.y, i0a);  i0b = f2fma(wB, L3.y, i0b);
    i1a = f2fma(wA, L4.x, i1a);  i1b = f2fma(wB, L4.x, i1b);
    i2a = f2fma(wA, L4.y, i2a);  i2b = f2fma(wB, L4.y, i2b);
    Ta  = f2fma(wA, NEG1, Ta);   Tb  = f2fma(wB, NEG1, Tb);
}

// Single fused kernel: per-block redundant prep (sort + preprocess, ~3KB inputs,
// L2-resident) -> per-tile cull + compaction -> 4px/thread composite.
__global__ void __launch_bounds__(RBLK)
render_kernel(float* __restrict__ out,
              const float* __restrict__ pos,
              const float* __restrict__ ls,
              const float* __restrict__ rop,
              const float* __restrict__ col) {
    __shared__ ulonglong2 sd[(NG + 1) * 5];      // sorted dup table (+null slot)
    __shared__ u64 keys[NG];
    __shared__ __align__(8) unsigned short sidx[NG + 4];
    __shared__ int scnt[8];
    __shared__ int s_n4;

    int t = threadIdx.x;
    int bid = blockIdx.x;
    int lane = t & 31;

    // ---- fused prep phase 1: sort keys (stable argsort by z) ----
    // key = (monotone_bits(z) << 32) | index  -> ascending key == stable z-order
    #pragma unroll
    for (int j = 0; j < 4; j++) {
        int gi = j * RBLK + t;
        float z = pos[3 * gi + 2];
        int b = __float_as_int(z);
        unsigned ob = (b >= 0) ? ((unsigned)b + 0x80000000u) : ~(unsigned)b;
        keys[gi] = ((u64)ob << 32) | (unsigned)gi;
    }
    __syncthreads();

    u64 myk[4];
    int rk[4] = {0, 0, 0, 0};
    #pragma unroll
    for (int j = 0; j < 4; j++) myk[j] = keys[j * RBLK + t];
    for (int j = 0; j < NG; j++) {
        u64 kj = keys[j];                        // LDS broadcast
        #pragma unroll
        for (int m = 0; m < 4; m++) rk[m] += (kj < myk[m]);
    }

    // ---- fused prep phase 2: derived scalars, scatter to sorted table ----
    #pragma unroll
    for (int j = 0; j < 4; j++) {
        int gi = j * RBLK + t;
        float m0 = pos[3 * gi + 0];
        float m1 = pos[3 * gi + 1];
        float m2 = pos[3 * gi + 2];
        float s0 = S_CONST * expf(-2.0f * ls[3 * gi + 0]);
        float s1 = S_CONST * expf(-2.0f * ls[3 * gi + 1]);
        float s2 = S_CONST * expf(-2.0f * ls[3 * gi + 2]);
        float q0 = m0 * s0, q1 = m1 * s1, q2 = m2 * s2;
        float kp = q0 * m0 + q1 * m1 + q2 * m2;
        float a0 = 1.0f / (1.0f + expf(-rop[gi]));
        float kcol = log2f(a0) - kp;             // alpha = 2^(num^2/den + kcol)
        float c0 = 1.0f / (1.0f + expf(-col[3 * gi + 0]));
        float c1 = 1.0f / (1.0f + expf(-col[3 * gi + 1]));
        float c2 = 1.0f / (1.0f + expf(-col[3 * gi + 2]));

        int rnk = rk[j];
        sd[5 * rnk + 0] = make_ulonglong2(dup2(q0), dup2(q1));
        sd[5 * rnk + 1] = make_ulonglong2(dup2(q2), dup2(s0));
        sd[5 * rnk + 2] = make_ulonglong2(dup2(s1), dup2(s2));
        sd[5 * rnk + 3] = make_ulonglong2(dup2(kcol), dup2(c0));
        sd[5 * rnk + 4] = make_ulonglong2(dup2(c1), dup2(c2));
    }
    if (t == 0) {   // null gaussian (slot NG): alpha == 0 always, no NaN path
        sd[NG * 5 + 0] = make_ulonglong2(0ull, 0ull);
        sd[NG * 5 + 1] = make_ulonglong2(0ull, 0ull);
        sd[NG * 5 + 2] = make_ulonglong2(0ull, dup2(1.0f));
        sd[NG * 5 + 3] = make_ulonglong2(dup2(-100.0f), 0ull);
        sd[NG * 5 + 4] = make_ulonglong2(0ull, 0ull);
    }
    __syncthreads();

    // ---- tile extent: u in [u0, u0+63], v in [v0, v0+3] ----
    int u0 = (bid & 7) * RBLK;
    int v0 = (bid >> 3) * 4;
    float dxlo = ((float)u0 + 0.5f - 256.0f) * (1.0f / 500.0f);
    float dxhi = ((float)(u0 + RBLK - 1) + 0.5f - 256.0f) * (1.0f / 500.0f);
    float dylo = ((float)v0 + 0.5f - 256.0f) * (1.0f / 500.0f);
    float dyhi = ((float)v0 + 3.5f - 256.0f) * (1.0f / 500.0f);

    float mindx2 = (dxlo * dxhi <= 0.0f) ? 0.0f : fminf(dxlo * dxlo, dxhi * dxhi);
    float mindy2 = (dylo * dyhi <= 0.0f) ? 0.0f : fminf(dylo * dylo, dyhi * dyhi);
    float maxdx2 = fmaxf(dxlo * dxlo, dxhi * dxhi);
    float maxdy2 = fmaxf(dylo * dylo, dyhi * dyhi);
    float thr_min = 0.1f * rsqrtf(maxdx2 + maxdy2 + 1.0f);

    // ---- cull (reads low halves of the sorted dup table) ----
    unsigned km[4];
    bool     kf[4];
    #pragma unroll
    for (int j = 0; j < 4; j++) {
        int gi = j * RBLK + t;                   // SORTED index
        const float* f = (const float*)(sd + 5 * gi);
        float q0 = f[0], q1 = f[2], q2 = f[4], s0 = f[6];
        float s1 = f[8], s2 = f[10], kcol = f[12];

        float numhi = q2 + fmaxf(q0 * dxlo, q0 * dxhi) + fmaxf(q1 * dylo, q1 * dyhi);
        float numlo = q2 + fminf(q0 * dxlo, q0 * dxhi) + fminf(q1 * dylo, q1 * dyhi);
        float den_min = s0 * mindx2 + s1 * mindy2 + s2;     // > 0
        float num2max = fmaxf(numhi * numhi, numlo * numlo);

        float m_ub = numhi - thr_min * den_min;  // >= margin at every pixel
        float e_ub = num2max / den_min + kcol;   // >= exponent at every pixel
        bool keep = (m_ub > -1e-5f) && (e_ub > -26.0f);

        km[j] = __ballot_sync(0xffffffffu, keep);
        kf[j] = keep;
        if (lane == 0) scnt[j * 2 + (t >> 5)] = __popc(km[j]);
    }
    __syncthreads();

    // ---- ordered compaction into sidx (segments ascend with sorted index) ----
    #pragma unroll
    for (int j = 0; j < 4; j++) {
        if (kf[j]) {
            int seg = j * 2 + (t >> 5);
            int off = 0;
            #pragma unroll
            for (int s = 0; s < 8; s++) off += (s < seg) ? scnt[s] : 0;
            int rank = __popc(km[j] & ((1u << lane) - 1u));
            sidx[off + rank] = (unsigned short)(j * RBLK + t);
        }
    }
    if (t == 0) {
        int n = scnt[0] + scnt[1] + scnt[2] + scnt[3]
              + scnt[4] + scnt[5] + scnt[6] + scnt[7];
        int n4 = (n + 3) & ~3;
        for (int p = n; p < n4; p++) sidx[p] = (unsigned short)NG;
        s_n4 = n4;
    }
    __syncthreads();
    int n4 = s_n4;

    // ---- per-thread ray setup: column u0+t, rows v0..v0+3 ----
    int u = u0 + t;
    float dx  = ((float)u + 0.5f - 256.0f) * (1.0f / 500.0f);
    float dy0 = ((float)v0 + 0.5f - 256.0f) * (1.0f / 500.0f);
    float dy1 = ((float)v0 + 1.5f - 256.0f) * (1.0f / 500.0f);
    float dy2 = ((float)v0 + 2.5f - 256.0f) * (1.0f / 500.0f);
    float dy3 = ((float)v0 + 3.5f - 256.0f) * (1.0f / 500.0f);

    Ray4 r;
    r.d0   = dup2(dx);
    r.dd0  = f2mul(r.d0, r.d0);
    r.d1a  = pk(dy0, dy1);
    r.d1b  = pk(dy2, dy3);
    r.dd1a = f2mul(r.d1a, r.d1a);
    r.dd1b = f2mul(r.d1b, r.d1b);
    float dxx = dx * dx;
    r.ntpa = pk(-0.1f * rsqrtf(dxx + dy0 * dy0 + 1.0f),
                -0.1f * rsqrtf(dxx + dy1 * dy1 + 1.0f));
    r.ntpb = pk(-0.1f * rsqrtf(dxx + dy2 * dy2 + 1.0f),
                -0.1f * rsqrtf(dxx + dy3 * dy3 + 1.0f));

    u64 Ta = pk(1.0f, 1.0f), Tb = Ta;
    u64 i0a = 0ull, i1a = 0ull, i2a = 0ull;
    u64 i0b = 0ull, i1b = 0ull, i2b = 0ull;

    // ---- main loop over surviving gaussians ----
    for (int g = 0; g < n4; g += 4) {
        ushort4 idx4 = *reinterpret_cast<const ushort4*>(sidx + g);  // 8B aligned
        comp_step4(sd + 5 * (int)idx4.x, r, Ta, i0a, i1a, i2a, Tb, i0b, i1b, i2b);
        comp_step4(sd + 5 * (int)idx4.y, r, Ta, i0a, i1a, i2a, Tb, i0b, i1b, i2b);
        comp_step4(sd + 5 * (int)idx4.z, r, Ta, i0a, i1a, i2a, Tb, i0b, i1b, i2b);
        comp_step4(sd + 5 * (int)idx4.w, r, Ta, i0a, i1a, i2a, Tb, i0b, i1b, i2b);

        float t0, t1, t2, t3;
        upk(Ta, t0, t1);
        upk(Tb, t2, t3);
        float tm = fmaxf(fmaxf(t0, t1), fmaxf(t2, t3));
        if (__all_sync(0xffffffffu, tm < 1e-5f)) break;
    }

    // ---- write 4 pixels x 3 channels ----
    float a, b, Tl, Th;
    int p0 = (v0 + 0) * IMG_W + u;
    int p1 = (v0 + 1) * IMG_W + u;
    upk(Ta, Tl, Th);
    upk(i0a, a, b); out[3 * p0 + 0] = a + Tl; out[3 * p1 + 0] = b + Th;
    upk(i1a, a, b); out[3 * p0 + 1] = a + Tl; out[3 * p1 + 1] = b + Th;
    upk(i2a, a, b); out[3 * p0 + 2] = a + Tl; out[3 * p1 + 2] = b + Th;
    int p2 = (v0 + 2) * IMG_W + u;
    int p3 = (v0 + 3) * IMG_W + u;
    upk(Tb, Tl, Th);
    upk(i0b, a, b); out[3 * p2 + 0] = a + Tl; out[3 * p3 + 0] = b + Th;
    upk(i1b, a, b); out[3 * p2 + 1] = a + Tl; out[3 * p3 + 1] = b + Th;
    upk(i2b, a, b); out[3 * p2 + 2] = a + Tl; out[3 * p3 + 2] = b + Th;
}

extern "C" void kernel_launch(void* const* d_in, const int* in_sizes, int n_in,
                              void* d_out, int out_size) {
    const float* positions   = (const float*)d_in[0];
    const float* log_scales  = (const float*)d_in[1];
    const float* raw_opacity = (const float*)d_in[2];
    const float* colors      = (const float*)d_in[3];
    float* out = (float*)d_out;

    render_kernel<<<(IMG_H * IMG_W) / (4 * RBLK), RBLK>>>(
        out, positions, log_scales, raw_opacity, colors);
}